// round 1
// baseline (speedup 1.0000x reference)
#include <cuda_runtime.h>
#include <cuda_bf16.h>
#include <math.h>

// ---------------------------------------------------------------------------
// Shapes
// ---------------------------------------------------------------------------
#define BB 32
#define LL 128
#define NN 512
#define JJ 21
#define HAND_DIM 99
#define DD 512
#define HH 8
#define DHH 64
#define DFF 2048
#define CAT 1249
#define SS 256            // 2*L
#define ROWS 4096         // B*L
#define TROWS 8192        // B*S

// feature layout offsets
#define F_X 0
#define F_J 99
#define F_MC 162
#define F_PCN 674
#define F_ATT 1186

// ---------------------------------------------------------------------------
// Scratch (device globals; static module allocation, allowed)
// ---------------------------------------------------------------------------
__device__ float g_feat_l[ROWS * CAT];
__device__ float g_feat_r[ROWS * CAT];
__device__ float g_x [TROWS * DD];
__device__ float g_q [TROWS * DD];
__device__ float g_k [TROWS * DD];
__device__ float g_v [TROWS * DD];
__device__ float g_ao [TROWS * DD];
__device__ float g_proj[TROWS * DD];
__device__ float g_x1 [TROWS * DD];
__device__ float g_h [TROWS * DFF];
__device__ float g_f [TROWS * DD];
__device__ float g_x2 [TROWS * DD];

// ---------------------------------------------------------------------------
// Kernel 1: build feature rows [x(99) | j(63) | mc(512) | pcn(512) | att(63)]
// One block per (b,l). Point cloud in smem; warp-argmin per joint matching
// jnp.argmin first-occurrence tie-break.
// ---------------------------------------------------------------------------
__global__ void build_features_kernel(
    const float* __restrict__ x_l, const float* __restrict__ x_r,
    const float* __restrict__ j_l, const float* __restrict__ j_r,
    const float* __restrict__ m_contact, const float* __restrict__ pc,
    float* __restrict__ feat_l, float* __restrict__ feat_r)
{
    int m = blockIdx.x;            // b*128 + l
    int b = m >> 7;
    __shared__ float px[NN], py[NN], pz[NN];
    int tid = threadIdx.x;

    const float* pcb = pc + (size_t)m * NN * 3;
    for (int n = tid; n < NN; n += 256) {
        px[n] = pcb[n*3+0];
        py[n] = pcb[n*3+1];
        pz[n] = pcb[n*3+2];
    }
    __syncthreads();

    float* fl = feat_l + (size_t)m * CAT;
    float* fr = feat_r + (size_t)m * CAT;

    for (int i = tid; i < HAND_DIM; i += 256) {
        fl[F_X+i] = x_l[(size_t)m*HAND_DIM + i];
        fr[F_X+i] = x_r[(size_t)m*HAND_DIM + i];
    }
    for (int i = tid; i < JJ*3; i += 256) {
        fl[F_J+i] = j_l[(size_t)m*JJ*3 + i];
        fr[F_J+i] = j_r[(size_t)m*JJ*3 + i];
    }
    for (int n = tid; n < NN; n += 256) {
        float mc = m_contact[b*NN + n];
        fl[F_MC+n] = mc; fr[F_MC+n] = mc;
        float nm = sqrtf(px[n]*px[n] + py[n]*py[n] + pz[n]*pz[n]);
        fl[F_PCN+n] = nm; fr[F_PCN+n] = nm;
    }

    int w = tid >> 5, lane = tid & 31;
    for (int task = w; task < 2*JJ; task += 8) {
        int hand = task / JJ, joint = task % JJ;
        const float* jb = (hand == 0 ? j_l : j_r) + ((size_t)m*JJ + joint)*3;
        float jx = jb[0], jy = jb[1], jz = jb[2];
        float best = 3.402823466e+38f; int bi = 0;
        for (int n = lane; n < NN; n += 32) {
            float dx = jx - px[n], dy = jy - py[n], dz = jz - pz[n];
            float d2 = dx*dx + dy*dy + dz*dz;
            if (d2 < best) { best = d2; bi = n; }
        }
        for (int off = 16; off; off >>= 1) {
            float ob = __shfl_xor_sync(0xffffffffu, best, off);
            int   oi = __shfl_xor_sync(0xffffffffu, bi, off);
            if (ob < best || (ob == best && oi < bi)) { best = ob; bi = oi; }
        }
        if (lane == 0) {
            float dx = jx - px[bi], dy = jy - py[bi], dz = jz - pz[bi];
            float* f = (hand == 0 ? fl : fr);
            f[F_ATT + joint*3 + 0] = expf(-50.f * dx * dx);
            f[F_ATT + joint*3 + 1] = expf(-50.f * dy * dy);
            f[F_ATT + joint*3 + 2] = expf(-50.f * dz * dz);
        }
    }
}

// ---------------------------------------------------------------------------
// Generic 128x128x8 register-blocked fp32 GEMM, 256 threads, 8x8 per thread.
// EPI=0: C = A@B (+bias) (+relu)
// EPI=1: fc epilogue: +bias +frame-PE +agent-PE, *mask*fpm  (interleaved C)
// EPI=2: out epilogue: +bias, *mask*fpm
// A has leading dimension lda (allows reading interleaved rows of g_x2).
// ---------------------------------------------------------------------------
struct EpiParams {
    const float* bias;
    const float* mask;           // [4096]
    const unsigned char* pad;    // [8192] bool
    int hand;
    int relu;
};

#define LN10000 9.2103403719761827f

template<int EPI>
__global__ __launch_bounds__(256)
void gemm128(const float* __restrict__ A, int lda,
             const float* __restrict__ B, int ldb,
             float* __restrict__ C, int ldc,
             int M, int N, int K, EpiParams ep)
{
    __shared__ float As[8][128];
    __shared__ float Bs[8][128];
    int tid = threadIdx.x;
    int tx = tid & 15, ty = tid >> 4;
    int m0 = blockIdx.y * 128, n0 = blockIdx.x * 128;

    float acc[8][8];
    #pragma unroll
    for (int i = 0; i < 8; i++)
        #pragma unroll
        for (int j = 0; j < 8; j++) acc[i][j] = 0.f;

    int arow = tid >> 1;
    int ak   = (tid & 1) * 4;

    for (int k0 = 0; k0 < K; k0 += 8) {
        #pragma unroll
        for (int i = 0; i < 4; i++) {
            int k = k0 + ak + i;
            As[ak+i][arow] = (k < K) ? A[(size_t)(m0+arow)*lda + k] : 0.f;
        }
        #pragma unroll
        for (int i = 0; i < 4; i++) {
            int idx = tid + 256*i;
            int r = idx >> 7, c = idx & 127;
            int k = k0 + r;
            Bs[r][c] = (k < K && (n0 + c) < N) ? B[(size_t)k*ldb + n0 + c] : 0.f;
        }
        __syncthreads();
        #pragma unroll
        for (int k = 0; k < 8; k++) {
            float4 a0 = *(const float4*)&As[k][ty*8];
            float4 a1 = *(const float4*)&As[k][ty*8+4];
            float4 b0 = *(const float4*)&Bs[k][tx*8];
            float4 b1 = *(const float4*)&Bs[k][tx*8+4];
            float ra[8] = {a0.x,a0.y,a0.z,a0.w,a1.x,a1.y,a1.z,a1.w};
            float rb[8] = {b0.x,b0.y,b0.z,b0.w,b1.x,b1.y,b1.z,b1.w};
            #pragma unroll
            for (int i = 0; i < 8; i++)
                #pragma unroll
                for (int j = 0; j < 8; j++)
                    acc[i][j] += ra[i]*rb[j];
        }
        __syncthreads();
    }

    #pragma unroll
    for (int i = 0; i < 8; i++) {
        int row = m0 + ty*8 + i;
        if (row >= M) continue;
        #pragma unroll
        for (int j = 0; j < 8; j++) {
            int col = n0 + tx*8 + j;
            if (col >= N) continue;
            float v = acc[i][j];
            if (EPI == 0) {
                if (ep.bias) v += ep.bias[col];
                if (ep.relu) v = fmaxf(v, 0.f);
            } else if (EPI == 1) {
                int l = row & 127;
                int ii = col >> 1;
                float freq = expf(-LN10000 * (float)ii * (1.f/256.f));
                float angF = (float)l * freq;
                float angA = (float)ep.hand * freq;
                float pe = (col & 1) ? (cosf(angF) + cosf(angA))
                                     : (sinf(angF) + sinf(angA));
                float mv = ep.mask[row] * (ep.pad[2*row + ep.hand] ? 0.f : 1.f);
                v = (v + ep.bias[col] + pe) * mv;
            } else { // EPI == 2
                float mv = ep.mask[row] * (ep.pad[2*row + ep.hand] ? 0.f : 1.f);
                v = (v + ep.bias[col]) * mv;
            }
            C[(size_t)row*ldc + col] = v;
        }
    }
}

// ---------------------------------------------------------------------------
// Fused attention: one block per (b,h). K,V (256x64) resident in smem.
// Each warp processes one q-row at a time: scores -> softmax -> P@V.
// ---------------------------------------------------------------------------
#define KV_PITCH 65
#define ATT_SMEM ((2*256*KV_PITCH + 8*256 + 8*64 + 256) * (int)sizeof(float))

__global__ void attention_kernel(const float* __restrict__ qb,
                                 const float* __restrict__ kb,
                                 const float* __restrict__ vb,
                                 const unsigned char* __restrict__ pad,
                                 float* __restrict__ ob)
{
    int bh = blockIdx.x;
    int b = bh >> 3, h = bh & 7;
    extern __shared__ float sm[];
    float* Ks = sm;                       // [256][65]
    float* Vs = Ks + 256*KV_PITCH;        // [256][65]
    float* Ps = Vs + 256*KV_PITCH;        // [8][256]
    float* Qs = Ps + 8*256;               // [8][64]
    float* Bsb = Qs + 8*64;               // [256] additive bias

    int tid = threadIdx.x, lane = tid & 31, w = tid >> 5;
    const float* kbase = kb + (size_t)(b*SS)*DD + h*DHH;
    const float* vbase = vb + (size_t)(b*SS)*DD + h*DHH;

    for (int idx = tid; idx < 256*64; idx += 256) {
        int r = idx >> 6, c = idx & 63;
        Ks[r*KV_PITCH + c] = kbase[(size_t)r*DD + c];
        Vs[r*KV_PITCH + c] = vbase[(size_t)r*DD + c];
    }
    if (tid < 256) Bsb[tid] = pad[b*SS + tid] ? -1e9f : 0.f;
    __syncthreads();

    float* Pw = Ps + w*256;
    float* Qw = Qs + w*64;

    for (int qi = w; qi < SS; qi += 8) {
        const float* qrow = qb + (size_t)(b*SS + qi)*DD + h*DHH;
        Qw[lane]      = qrow[lane];
        Qw[lane + 32] = qrow[lane + 32];
        __syncwarp();

        float s[8];
        float mx = -3.402823466e+38f;
        #pragma unroll
        for (int k8 = 0; k8 < 8; k8++) {
            int j = lane + 32*k8;
            const float* kr = Ks + j*KV_PITCH;
            float acc = 0.f;
            #pragma unroll
            for (int d = 0; d < 64; d++) acc += Qw[d]*kr[d];
            acc = acc * 0.125f + Bsb[j];
            s[k8] = acc;
            mx = fmaxf(mx, acc);
        }
        for (int off = 16; off; off >>= 1)
            mx = fmaxf(mx, __shfl_xor_sync(0xffffffffu, mx, off));
        float sum = 0.f;
        #pragma unroll
        for (int k8 = 0; k8 < 8; k8++) { s[k8] = __expf(s[k8]-mx); sum += s[k8]; }
        for (int off = 16; off; off >>= 1)
            sum += __shfl_xor_sync(0xffffffffu, sum, off);
        float inv = 1.f / sum;
        #pragma unroll
        for (int k8 = 0; k8 < 8; k8++) Pw[lane + 32*k8] = s[k8]*inv;
        __syncwarp();

        float o0 = 0.f, o1 = 0.f;
        for (int j = 0; j < 256; j++) {
            float p = Pw[j];
            o0 += p * Vs[j*KV_PITCH + lane];
            o1 += p * Vs[j*KV_PITCH + lane + 32];
        }
        float* orow = ob + (size_t)(b*SS + qi)*DD + h*DHH;
        orow[lane]      = o0;
        orow[lane + 32] = o1;
        __syncwarp();
    }
}

// ---------------------------------------------------------------------------
// Residual add + LayerNorm (post-LN). One block per token row.
// ---------------------------------------------------------------------------
__global__ void ln_kernel(const float* __restrict__ x, const float* __restrict__ add,
                          const float* __restrict__ g, const float* __restrict__ bv,
                          float* __restrict__ out)
{
    int t = blockIdx.x;
    int tid = threadIdx.x;            // 128
    const float* xr = x   + (size_t)t*DD;
    const float* ar = add + (size_t)t*DD;
    float v[4];
    float s = 0.f, ss = 0.f;
    #pragma unroll
    for (int i = 0; i < 4; i++) {
        float u = xr[tid + 128*i] + ar[tid + 128*i];
        v[i] = u; s += u; ss += u*u;
    }
    for (int off = 16; off; off >>= 1) {
        s  += __shfl_xor_sync(0xffffffffu, s,  off);
        ss += __shfl_xor_sync(0xffffffffu, ss, off);
    }
    __shared__ float rs[4], rss[4];
    int w = tid >> 5, lane = tid & 31;
    if (lane == 0) { rs[w] = s; rss[w] = ss; }
    __syncthreads();
    s  = rs[0]+rs[1]+rs[2]+rs[3];
    ss = rss[0]+rss[1]+rss[2]+rss[3];
    float mean = s * (1.f/512.f);
    float var  = ss * (1.f/512.f) - mean*mean;
    float rstd = rsqrtf(var + 1e-5f);
    #pragma unroll
    for (int i = 0; i < 4; i++) {
        int c = tid + 128*i;
        out[(size_t)t*DD + c] = (v[i]-mean)*rstd*g[c] + bv[c];
    }
}

// ---------------------------------------------------------------------------
// Launch
// ---------------------------------------------------------------------------
extern "C" void kernel_launch(void* const* d_in, const int* in_sizes, int n_in,
                              void* d_out, int out_size)
{
    const float* x_l  = (const float*)d_in[0];
    const float* x_r  = (const float*)d_in[1];
    const float* j_l  = (const float*)d_in[2];
    const float* j_r  = (const float*)d_in[3];
    const float* mcon = (const float*)d_in[4];
    const float* pc   = (const float*)d_in[5];
    const float* mask_l = (const float*)d_in[6];
    const float* mask_r = (const float*)d_in[7];
    const unsigned char* pad = (const unsigned char*)d_in[8];
    const float* W_fc_l = (const float*)d_in[9];
    const float* b_fc_l = (const float*)d_in[10];
    const float* W_fc_r = (const float*)d_in[11];
    const float* b_fc_r = (const float*)d_in[12];
    const float* Wq = (const float*)d_in[13];
    const float* Wk = (const float*)d_in[14];
    const float* Wv = (const float*)d_in[15];
    const float* Wo = (const float*)d_in[16];
    const float* W1 = (const float*)d_in[17];
    const float* b1 = (const float*)d_in[18];
    const float* W2 = (const float*)d_in[19];
    const float* b2 = (const float*)d_in[20];
    const float* ln1g = (const float*)d_in[21];
    const float* ln1b = (const float*)d_in[22];
    const float* ln2g = (const float*)d_in[23];
    const float* ln2b = (const float*)d_in[24];
    const float* W_out_l = (const float*)d_in[25];
    const float* b_out_l = (const float*)d_in[26];
    const float* W_out_r = (const float*)d_in[27];
    const float* b_out_r = (const float*)d_in[28];
    float* outp = (float*)d_out;

    float *pfl, *pfr, *px, *pq, *pk, *pv, *pao, *pproj, *px1, *ph, *pf, *px2;
    cudaGetSymbolAddress((void**)&pfl,  g_feat_l);
    cudaGetSymbolAddress((void**)&pfr,  g_feat_r);
    cudaGetSymbolAddress((void**)&px,   g_x);
    cudaGetSymbolAddress((void**)&pq,   g_q);
    cudaGetSymbolAddress((void**)&pk,   g_k);
    cudaGetSymbolAddress((void**)&pv,   g_v);
    cudaGetSymbolAddress((void**)&pao,  g_ao);
    cudaGetSymbolAddress((void**)&pproj,g_proj);
    cudaGetSymbolAddress((void**)&px1,  g_x1);
    cudaGetSymbolAddress((void**)&ph,   g_h);
    cudaGetSymbolAddress((void**)&pf,   g_f);
    cudaGetSymbolAddress((void**)&px2,  g_x2);

    // 1. features
    build_features_kernel<<<ROWS, 256>>>(x_l, x_r, j_l, j_r, mcon, pc, pfl, pfr);

    // 2. fc projections -> interleaved x with PE + masks
    EpiParams fc_el = {b_fc_l, mask_l, pad, 0, 0};
    EpiParams fc_er = {b_fc_r, mask_r, pad, 1, 0};
    gemm128<1><<<dim3(4,32), 256>>>(pfl, CAT, W_fc_l, DD, px,        2*DD, ROWS, DD, CAT, fc_el);
    gemm128<1><<<dim3(4,32), 256>>>(pfr, CAT, W_fc_r, DD, px + DD,   2*DD, ROWS, DD, CAT, fc_er);

    // 3. QKV
    EpiParams none = {nullptr, nullptr, nullptr, 0, 0};
    gemm128<0><<<dim3(4,64), 256>>>(px, DD, Wq, DD, pq, DD, TROWS, DD, DD, none);
    gemm128<0><<<dim3(4,64), 256>>>(px, DD, Wk, DD, pk, DD, TROWS, DD, DD, none);
    gemm128<0><<<dim3(4,64), 256>>>(px, DD, Wv, DD, pv, DD, TROWS, DD, DD, none);

    // 4. fused attention
    cudaFuncSetAttribute(attention_kernel,
                         cudaFuncAttributeMaxDynamicSharedMemorySize, ATT_SMEM);
    attention_kernel<<<BB*HH, 256, ATT_SMEM>>>(pq, pk, pv, pad, pao);

    // 5. output projection + LN1
    gemm128<0><<<dim3(4,64), 256>>>(pao, DD, Wo, DD, pproj, DD, TROWS, DD, DD, none);
    ln_kernel<<<TROWS, 128>>>(px, pproj, ln1g, ln1b, px1);

    // 6. FFN + LN2
    EpiParams e1 = {b1, nullptr, nullptr, 0, 1};
    EpiParams e2 = {b2, nullptr, nullptr, 0, 0};
    gemm128<0><<<dim3(16,64), 256>>>(px1, DD, W1, DFF, ph, DFF, TROWS, DFF, DD, e1);
    gemm128<0><<<dim3(4,64),  256>>>(ph, DFF, W2, DD, pf, DD, TROWS, DD, DFF, e2);
    ln_kernel<<<TROWS, 128>>>(px1, pf, ln2g, ln2b, px2);

    // 7. per-hand output heads (A reads interleaved rows via lda=2*DD)
    EpiParams ol = {b_out_l, mask_l, pad, 0, 0};
    EpiParams orr= {b_out_r, mask_r, pad, 1, 0};
    gemm128<2><<<dim3(1,32), 256>>>(px2,      2*DD, W_out_l, HAND_DIM,
                                    outp,                 HAND_DIM, ROWS, HAND_DIM, DD, ol);
    gemm128<2><<<dim3(1,32), 256>>>(px2 + DD, 2*DD, W_out_r, HAND_DIM,
                                    outp + ROWS*HAND_DIM, HAND_DIM, ROWS, HAND_DIM, DD, orr);
}